// round 6
// baseline (speedup 1.0000x reference)
#include <cuda_runtime.h>

#define BSZ 512
#define IN_DIM 128
#define H2 512
#define OUT_DIM 25
#define NPOLY 33   // Taylor terms m = 0..32

// Scratch (static device globals — no allocation)
__device__ float g_h[BSZ * H2];
__device__ float g_Q[BSZ * H2];
__device__ float g_K[BSZ * H2];
__device__ float g_V[BSZ * H2];

__constant__ float c_invfact[NPOLY] = {
    1.0f, 1.0f, 5.0000000e-01f, 1.6666667e-01f, 4.1666667e-02f,
    8.3333333e-03f, 1.3888889e-03f, 1.9841270e-04f, 2.4801587e-05f,
    2.7557319e-06f, 2.7557319e-07f, 2.5052108e-08f, 2.0876757e-09f,
    1.6059044e-10f, 1.1470746e-11f, 7.6471637e-13f, 4.7794773e-14f,
    2.8114573e-15f, 1.5619207e-16f, 8.2206352e-18f, 4.1103176e-19f,
    1.9572941e-20f, 8.8967914e-22f, 3.8681702e-23f, 1.6117376e-24f,
    6.4469503e-26f, 2.4795963e-27f, 9.1836898e-29f, 3.2798892e-30f,
    1.1309962e-31f, 3.7699876e-33f, 1.2161250e-34f, 3.8003907e-36f
};

__device__ __forceinline__ float ex2f(float x) {
    float y;
    asm("ex2.approx.ftz.f32 %0, %1;" : "=f"(y) : "f"(x));
    return y;
}

__device__ __forceinline__ float siluf(float x) {
    float e = ex2f(-1.44269504f * x);
    return __fdividef(x, 1.0f + e);
}

__device__ __forceinline__ unsigned long long dup2(float x) {
    unsigned long long r;
    asm("mov.b64 %0, {%1, %1};" : "=l"(r) : "f"(x));
    return r;
}
__device__ __forceinline__ void ffma2(unsigned long long& d,
                                      unsigned long long a,
                                      unsigned long long b) {
    asm("fma.rn.f32x2 %0, %1, %2, %0;" : "+l"(d) : "l"(a), "l"(b));
}
__device__ __forceinline__ void unpack2(unsigned long long v, float& lo, float& hi) {
    asm("mov.b64 {%0, %1}, %2;" : "=f"(lo), "=f"(hi) : "l"(v));
}

// ---------------------------------------------------------------------------
// gemm1: C = silu(A[M,128] @ W[N,128]^T + bias). 32x32 tile, 128 threads.
// ---------------------------------------------------------------------------
__global__ void __launch_bounds__(128) gemm1_silu_kernel(
    const float* __restrict__ A,
    const float* __restrict__ W,
    const float* __restrict__ bias,
    float* __restrict__ C,
    int N, int Kd)
{
    __shared__ float As[2][16][36];
    __shared__ float Ws[2][16][36];

    const int tid  = threadIdx.x;
    const int tx   = tid & 7;
    const int ty   = tid >> 3;
    const int row0 = blockIdx.y * 32;
    const int col0 = blockIdx.x * 32;

    const int lrow = tid >> 2;
    const int lk   = (tid & 3) * 4;

    unsigned long long acc[4];
#pragma unroll
    for (int c = 0; c < 4; c++) acc[c] = 0ull;

    const int nk = Kd >> 4;
    float4 pa, pw;

    {
        pa = *(const float4*)&A[(row0 + lrow) * Kd + lk];
        pw = *(const float4*)&W[(col0 + lrow) * Kd + lk];
        As[0][lk + 0][lrow] = pa.x; As[0][lk + 1][lrow] = pa.y;
        As[0][lk + 2][lrow] = pa.z; As[0][lk + 3][lrow] = pa.w;
        Ws[0][lk + 0][lrow] = pw.x; Ws[0][lk + 1][lrow] = pw.y;
        Ws[0][lk + 2][lrow] = pw.z; Ws[0][lk + 3][lrow] = pw.w;
    }
    __syncthreads();

    for (int t = 0; t < nk; t++) {
        const int cur = t & 1;
        if (t + 1 < nk) {
            const int k0 = (t + 1) * 16;
            pa = *(const float4*)&A[(row0 + lrow) * Kd + k0 + lk];
            pw = *(const float4*)&W[(col0 + lrow) * Kd + k0 + lk];
        }

#pragma unroll
        for (int kk = 0; kk < 16; kk++) {
            const unsigned long long a =
                *(const unsigned long long*)&As[cur][kk][ty * 2];
            const float4 w = *(const float4*)&Ws[cur][kk][tx * 4];
            ffma2(acc[0], a, dup2(w.x));
            ffma2(acc[1], a, dup2(w.y));
            ffma2(acc[2], a, dup2(w.z));
            ffma2(acc[3], a, dup2(w.w));
        }

        if (t + 1 < nk) {
            const int nb = (t + 1) & 1;
            As[nb][lk + 0][lrow] = pa.x; As[nb][lk + 1][lrow] = pa.y;
            As[nb][lk + 2][lrow] = pa.z; As[nb][lk + 3][lrow] = pa.w;
            Ws[nb][lk + 0][lrow] = pw.x; Ws[nb][lk + 1][lrow] = pw.y;
            Ws[nb][lk + 2][lrow] = pw.z; Ws[nb][lk + 3][lrow] = pw.w;
            __syncthreads();
        }
    }

    float bz[4];
#pragma unroll
    for (int c = 0; c < 4; c++) bz[c] = bias[col0 + tx * 4 + c];

    float r0[4], r1[4];
#pragma unroll
    for (int c = 0; c < 4; c++) unpack2(acc[c], r0[c], r1[c]);
    float* Crow0 = C + (row0 + ty * 2) * N + col0 + tx * 4;
    float* Crow1 = Crow0 + N;
    float4 o;
    o.x = siluf(r0[0] + bz[0]); o.y = siluf(r0[1] + bz[1]);
    o.z = siluf(r0[2] + bz[2]); o.w = siluf(r0[3] + bz[3]);
    *(float4*)Crow0 = o;
    o.x = siluf(r1[0] + bz[0]); o.y = siluf(r1[1] + bz[1]);
    o.z = siluf(r1[2] + bz[2]); o.w = siluf(r1[3] + bz[3]);
    *(float4*)Crow1 = o;
}

// ---------------------------------------------------------------------------
// QKV GEMM: 32x64 tile, 128 threads, 4x4 per thread (unchanged from R5).
// ---------------------------------------------------------------------------
__global__ void __launch_bounds__(128) gemm_silu_kernel(
    const float* __restrict__ A,
    const float* __restrict__ W0, const float* __restrict__ W1, const float* __restrict__ W2,
    const float* __restrict__ bias0, const float* __restrict__ bias1, const float* __restrict__ bias2,
    float* __restrict__ C0, float* __restrict__ C1, float* __restrict__ C2,
    int N, int Kd)
{
    const float* W    = (blockIdx.z == 0) ? W0    : (blockIdx.z == 1) ? W1    : W2;
    const float* bias = (blockIdx.z == 0) ? bias0 : (blockIdx.z == 1) ? bias1 : bias2;
    float*       C    = (blockIdx.z == 0) ? C0    : (blockIdx.z == 1) ? C1    : C2;

    __shared__ float As[2][16][36];
    __shared__ float Ws[2][16][68];

    const int tid  = threadIdx.x;
    const int tx   = tid & 15;
    const int ty   = tid >> 4;
    const int row0 = blockIdx.y * 32;
    const int col0 = blockIdx.x * 64;

    const int alrow = tid >> 2;
    const int alk   = (tid & 3) * 4;
    const int wlrow = tid >> 1;
    const int wlk   = (tid & 1) * 8;

    unsigned long long acc[2][4];
#pragma unroll
    for (int p = 0; p < 2; p++)
#pragma unroll
        for (int c = 0; c < 4; c++) acc[p][c] = 0ull;

    const int nk = Kd >> 4;
    float4 pa, pw0, pw1;

    {
        pa  = *(const float4*)&A[(row0 + alrow) * Kd + alk];
        pw0 = *(const float4*)&W[(col0 + wlrow) * Kd + wlk];
        pw1 = *(const float4*)&W[(col0 + wlrow) * Kd + wlk + 4];
        As[0][alk + 0][alrow] = pa.x; As[0][alk + 1][alrow] = pa.y;
        As[0][alk + 2][alrow] = pa.z; As[0][alk + 3][alrow] = pa.w;
        Ws[0][wlk + 0][wlrow] = pw0.x; Ws[0][wlk + 1][wlrow] = pw0.y;
        Ws[0][wlk + 2][wlrow] = pw0.z; Ws[0][wlk + 3][wlrow] = pw0.w;
        Ws[0][wlk + 4][wlrow] = pw1.x; Ws[0][wlk + 5][wlrow] = pw1.y;
        Ws[0][wlk + 6][wlrow] = pw1.z; Ws[0][wlk + 7][wlrow] = pw1.w;
    }
    __syncthreads();

    for (int t = 0; t < nk; t++) {
        const int cur = t & 1;
        if (t + 1 < nk) {
            const int k0 = (t + 1) * 16;
            pa  = *(const float4*)&A[(row0 + alrow) * Kd + k0 + alk];
            pw0 = *(const float4*)&W[(col0 + wlrow) * Kd + k0 + wlk];
            pw1 = *(const float4*)&W[(col0 + wlrow) * Kd + k0 + wlk + 4];
        }

#pragma unroll
        for (int kk = 0; kk < 16; kk++) {
            const ulonglong2 a =
                *(const ulonglong2*)&As[cur][kk][ty * 4];
            const float4 w = *(const float4*)&Ws[cur][kk][tx * 4];
            const unsigned long long w0 = dup2(w.x);
            const unsigned long long w1 = dup2(w.y);
            const unsigned long long w2 = dup2(w.z);
            const unsigned long long w3 = dup2(w.w);
            ffma2(acc[0][0], a.x, w0);
            ffma2(acc[1][0], a.y, w0);
            ffma2(acc[0][1], a.x, w1);
            ffma2(acc[1][1], a.y, w1);
            ffma2(acc[0][2], a.x, w2);
            ffma2(acc[1][2], a.y, w2);
            ffma2(acc[0][3], a.x, w3);
            ffma2(acc[1][3], a.y, w3);
        }

        if (t + 1 < nk) {
            const int nb = (t + 1) & 1;
            As[nb][alk + 0][alrow] = pa.x; As[nb][alk + 1][alrow] = pa.y;
            As[nb][alk + 2][alrow] = pa.z; As[nb][alk + 3][alrow] = pa.w;
            Ws[nb][wlk + 0][wlrow] = pw0.x; Ws[nb][wlk + 1][wlrow] = pw0.y;
            Ws[nb][wlk + 2][wlrow] = pw0.z; Ws[nb][wlk + 3][wlrow] = pw0.w;
            Ws[nb][wlk + 4][wlrow] = pw1.x; Ws[nb][wlk + 5][wlrow] = pw1.y;
            Ws[nb][wlk + 6][wlrow] = pw1.z; Ws[nb][wlk + 7][wlrow] = pw1.w;
            __syncthreads();
        }
    }

    float bz[4];
#pragma unroll
    for (int c = 0; c < 4; c++) bz[c] = bias[col0 + tx * 4 + c];

#pragma unroll
    for (int p = 0; p < 2; p++) {
        float r0[4], r1[4];
#pragma unroll
        for (int c = 0; c < 4; c++) unpack2(acc[p][c], r0[c], r1[c]);
        float* Crow0 = C + (row0 + ty * 4 + 2 * p) * N + col0 + tx * 4;
        float* Crow1 = Crow0 + N;
        float4 o;
        o.x = siluf(r0[0] + bz[0]); o.y = siluf(r0[1] + bz[1]);
        o.z = siluf(r0[2] + bz[2]); o.w = siluf(r0[3] + bz[3]);
        *(float4*)Crow0 = o;
        o.x = siluf(r1[0] + bz[0]); o.y = siluf(r1[1] + bz[1]);
        o.z = siluf(r1[2] + bz[2]); o.w = siluf(r1[3] + bz[3]);
        *(float4*)Crow1 = o;
    }
}

// ---------------------------------------------------------------------------
// Attention v2: rank-1 softmax, two exact fast paths.
//  - |q| small (q <= qc): Taylor-moment evaluation (33 terms), exact to <1e-8.
//  - q  large: K sorted descending; only top n_t terms with relative weight
//    >= 2^-27 are summed (binary-searched trip count).
//  q is bitonic-sorted so warps have coherent trip counts.
// Then output projection + quadratic epilogue (unchanged).
// ---------------------------------------------------------------------------
__global__ void __launch_bounds__(H2) attn_out_kernel(
    const float* __restrict__ W_out,
    const float* __restrict__ b_out,
    float* __restrict__ out)
{
    __shared__ float Kn[H2];        // natural K (original order, for moments)
    __shared__ float Vn[H2];        // V (original order)
    __shared__ float Ksrt[H2];      // K sorted descending
    __shared__ float Vsrt[H2];      // V permuted with Ksrt
    __shared__ float qs[H2];        // q sorted ascending
    __shared__ int   qidx[H2];      // original index payload
    __shared__ float cs[H2];        // ctx (original order)
    __shared__ float red[32];
    __shared__ float s_kmax;
    __shared__ float m1p[NPOLY][16];   // per-warp partial moments (plain)
    __shared__ float mvp[NPOLY][16];   // per-warp partial moments (V-weighted)
    __shared__ float c1[NPOLY], cV[NPOLY];
    __shared__ float ys[32];

    const int b = blockIdx.x;
    const int t = threadIdx.x;
    const int wid = t >> 5, lane = t & 31;

    const float kv = g_K[b * H2 + t];
    const float vv = g_V[b * H2 + t];
    const float qv = g_Q[b * H2 + t];
    Kn[t] = kv; Vn[t] = vv;
    Ksrt[t] = kv; Vsrt[t] = vv;
    qs[t] = qv; qidx[t] = t;

    // ---- block max of K ----
    float kmx = kv;
#pragma unroll
    for (int o = 16; o; o >>= 1)
        kmx = fmaxf(kmx, __shfl_xor_sync(0xFFFFFFFFu, kmx, o));
    if (lane == 0) red[wid] = kmx;
    __syncthreads();
    if (t == 0) {
        float a = red[0];
#pragma unroll
        for (int i = 1; i < 16; i++) a = fmaxf(a, red[i]);
        s_kmax = a;
    }
    __syncthreads();
    const float kmax = s_kmax;
    const float S    = fmaxf(kmax, 0.3f);       // poly scale base
    const float qc   = fmaxf(7.0f / S, 0.2786f); // poly/exp split point

    // ---- bitonic sort q ascending (payload: original index) ----
#pragma unroll 1
    for (int k = 2; k <= H2; k <<= 1) {
#pragma unroll 1
        for (int j = k >> 1; j > 0; j >>= 1) {
            const int p = t ^ j;
            const float a  = qs[t], bb = qs[p];
            const int   ia = qidx[p];
            __syncthreads();
            const bool dir = ((t & k) == 0);  // ascending
            const bool lower = (t < p);
            const float vlo = lower ? a : bb;
            const float vhi = lower ? bb : a;
            if ((vlo > vhi) == dir) { qs[t] = bb; qidx[t] = ia; }
            __syncthreads();
        }
    }

    // ---- bitonic sort K descending (payload: V) ----
#pragma unroll 1
    for (int k = 2; k <= H2; k <<= 1) {
#pragma unroll 1
        for (int j = k >> 1; j > 0; j >>= 1) {
            const int p = t ^ j;
            const float a  = Ksrt[t], bb = Ksrt[p];
            const float va = Vsrt[p];
            __syncthreads();
            const bool dir = ((t & k) != 0);  // descending overall
            const bool lower = (t < p);
            const float vlo = lower ? a : bb;
            const float vhi = lower ? bb : a;
            if ((vlo > vhi) == dir) { Ksrt[t] = bb; Vsrt[t] = va; }
            __syncthreads();
        }
    }

    // ---- moments: mu_m = sum_j r^m, muV_m = sum_j r^m * V ; r = K/S ----
    {
        const float r = Kn[t] / S;
        const float v = Vn[t];
        float pw = 1.0f;
#pragma unroll 1
        for (int m = 0; m < NPOLY; m++) {
            float s1 = pw, sv = pw * v;
#pragma unroll
            for (int o = 16; o; o >>= 1) {
                s1 += __shfl_xor_sync(0xFFFFFFFFu, s1, o);
                sv += __shfl_xor_sync(0xFFFFFFFFu, sv, o);
            }
            if (lane == 0) { m1p[m][wid] = s1; mvp[m][wid] = sv; }
            pw *= r;
        }
    }
    __syncthreads();
    if (t < NPOLY) {
        float a = 0.0f;
#pragma unroll
        for (int i = 0; i < 16; i++) a += m1p[t][i];
        c1[t] = a * c_invfact[t];
    } else if (t >= 64 && t < 64 + NPOLY) {
        const int m = t - 64;
        float a = 0.0f;
#pragma unroll
        for (int i = 0; i < 16; i++) a += mvp[m][i];
        cV[m] = a * c_invfact[m];
    }
    __syncthreads();

    // ---- per-thread ctx via poly or truncated-exp path ----
    const float q = qs[t];
    float ctx;
    if (q <= qc) {
        // Taylor-moment path: t-var = q*S, |t*r| <= max(7, 0.2786*S)
        const float tv = q * S;
        float num = cV[NPOLY - 1], den = c1[NPOLY - 1];
#pragma unroll
        for (int m = NPOLY - 2; m >= 0; m--) {
            num = fmaf(num, tv, cV[m]);
            den = fmaf(den, tv, c1[m]);
        }
        ctx = __fdividef(num, den);
    } else {
        // truncated sorted-exp path: keep K_j >= kmax - 27/(q*log2e)
        const float cutval = kmax - 18.714974f / q;   // 27/log2(e) = 18.715
        int lo = 0, hi = H2;
        while (lo < hi) {
            const int mid = (lo + hi) >> 1;
            if (Ksrt[mid] >= cutval) lo = mid + 1; else hi = mid;
        }
        const int n = lo;                      // >= 1 (Ksrt[0] = kmax passes)
        const float q2 = q * 1.44269504f;
        const float c2 = -q2 * kmax;
        float sE = 0.0f, sEV = 0.0f;
        for (int j = 0; j < n; j++) {
            const float e = ex2f(fmaf(q2, Ksrt[j], c2));
            sE += e;
            sEV = fmaf(e, Vsrt[j], sEV);
        }
        ctx = __fdividef(sEV, sE);
    }
    cs[qidx[t]] = siluf(ctx);
    __syncthreads();

    // ---- output projection: warp w handles n = w and n = w + 16 ----
#pragma unroll
    for (int r = 0; r < 2; r++) {
        const int n = wid + 16 * r;
        if (n < OUT_DIM) {
            const float* Wr = W_out + n * H2;
            float s = 0.0f;
#pragma unroll
            for (int kk = 0; kk < 16; kk++)
                s = fmaf(cs[lane + 32 * kk], Wr[lane + 32 * kk], s);
#pragma unroll
            for (int o = 16; o; o >>= 1)
                s += __shfl_xor_sync(0xFFFFFFFFu, s, o);
            if (lane == 0) ys[n] = siluf(s + b_out[n]);
        }
    }
    __syncthreads();

    if (t == 0) {
        float g[5];
#pragma unroll
        for (int gi = 0; gi < 5; gi++) {
            float s = 0.0f;
#pragma unroll
            for (int i = 0; i < 5; i++) {
                const float yv = ys[gi * 5 + i];
                s = fmaf(yv, yv, s);
            }
            g[gi] = s;
        }
        const float m11 = g[0], m12 = g[1], m21 = g[2], m22 = g[3], mpp = g[4];
        const float q0 = ys[0], q1 = ys[1], q2 = ys[2], q3 = ys[3];
        const float quad = m11 * (q0 * q0 + q1 * q1)
                         + (m12 + m21) * (q0 * q2 + q1 * q3)
                         + m22 * (q2 * q2 + q3 * q3);
        out[b] = quad + mpp;
    }
}

// ---------------------------------------------------------------------------
extern "C" void kernel_launch(void* const* d_in, const int* in_sizes, int n_in,
                              void* d_out, int out_size)
{
    const float* x     = (const float*)d_in[0];
    // d_in[1] = na (int32, always 4) — unused (q = y[:, :4] hardcoded)
    const float* W_in  = (const float*)d_in[2];
    const float* b_in  = (const float*)d_in[3];
    const float* Aq    = (const float*)d_in[4];
    const float* Bq    = (const float*)d_in[5];
    const float* Ak    = (const float*)d_in[6];
    const float* Bk    = (const float*)d_in[7];
    const float* Av    = (const float*)d_in[8];
    const float* Bv    = (const float*)d_in[9];
    const float* W_out = (const float*)d_in[10];
    const float* b_out = (const float*)d_in[11];
    float* out = (float*)d_out;

    float *h, *Qp, *Kp, *Vp;
    cudaGetSymbolAddress((void**)&h,  g_h);
    cudaGetSymbolAddress((void**)&Qp, g_Q);
    cudaGetSymbolAddress((void**)&Kp, g_K);
    cudaGetSymbolAddress((void**)&Vp, g_V);

    // h = silu(x @ W_in^T + b_in)
    gemm1_silu_kernel<<<dim3(16, 16), 128>>>(x, W_in, b_in, h, H2, IN_DIM);

    // Q,K,V = silu(h @ A*^T + B*) fused via grid.z
    gemm_silu_kernel<<<dim3(8, 16, 3), 128>>>(
        h, Aq, Ak, Av, Bq, Bk, Bv, Qp, Kp, Vp, H2, H2);

    // rank-1 softmax attention (poly + truncated-exp) + projection + epilogue
    attn_out_kernel<<<BSZ, H2>>>(W_out, b_out, out);
}

// round 8
// speedup vs baseline: 1.1430x; 1.1430x over previous
#include <cuda_runtime.h>

#define BSZ 512
#define IN_DIM 128
#define H2 512
#define OUT_DIM 25
#define NPOLY 33   // Taylor terms m = 0..32

// Scratch (static device globals — no allocation)
__device__ float g_h[BSZ * H2];
__device__ float g_Q[BSZ * H2];
__device__ float g_K[BSZ * H2];
__device__ float g_V[BSZ * H2];

__constant__ float c_invfact[NPOLY] = {
    1.0f, 1.0f, 5.0000000e-01f, 1.6666667e-01f, 4.1666667e-02f,
    8.3333333e-03f, 1.3888889e-03f, 1.9841270e-04f, 2.4801587e-05f,
    2.7557319e-06f, 2.7557319e-07f, 2.5052108e-08f, 2.0876757e-09f,
    1.6059044e-10f, 1.1470746e-11f, 7.6471637e-13f, 4.7794773e-14f,
    2.8114573e-15f, 1.5619207e-16f, 8.2206352e-18f, 4.1103176e-19f,
    1.9572941e-20f, 8.8967914e-22f, 3.8681702e-23f, 1.6117376e-24f,
    6.4469503e-26f, 2.4795963e-27f, 9.1836898e-29f, 3.2798892e-30f,
    1.1309962e-31f, 3.7699876e-33f, 1.2161250e-34f, 3.8003907e-36f
};

__device__ __forceinline__ float ex2f(float x) {
    float y;
    asm("ex2.approx.ftz.f32 %0, %1;" : "=f"(y) : "f"(x));
    return y;
}

__device__ __forceinline__ float siluf(float x) {
    float e = ex2f(-1.44269504f * x);
    return __fdividef(x, 1.0f + e);
}

__device__ __forceinline__ unsigned long long dup2(float x) {
    unsigned long long r;
    asm("mov.b64 %0, {%1, %1};" : "=l"(r) : "f"(x));
    return r;
}
__device__ __forceinline__ void ffma2(unsigned long long& d,
                                      unsigned long long a,
                                      unsigned long long b) {
    asm("fma.rn.f32x2 %0, %1, %2, %0;" : "+l"(d) : "l"(a), "l"(b));
}
__device__ __forceinline__ void unpack2(unsigned long long v, float& lo, float& hi) {
    asm("mov.b64 {%0, %1}, %2;" : "=f"(lo), "=f"(hi) : "l"(v));
}

// ---------------------------------------------------------------------------
// gemm1: C = silu(A[M,128] @ W[N,128]^T + bias). 32x32 tile, 128 threads.
// ---------------------------------------------------------------------------
__global__ void __launch_bounds__(128) gemm1_silu_kernel(
    const float* __restrict__ A,
    const float* __restrict__ W,
    const float* __restrict__ bias,
    float* __restrict__ C,
    int N, int Kd)
{
    __shared__ float As[2][16][36];
    __shared__ float Ws[2][16][36];

    const int tid  = threadIdx.x;
    const int tx   = tid & 7;
    const int ty   = tid >> 3;
    const int row0 = blockIdx.y * 32;
    const int col0 = blockIdx.x * 32;

    const int lrow = tid >> 2;
    const int lk   = (tid & 3) * 4;

    unsigned long long acc[4];
#pragma unroll
    for (int c = 0; c < 4; c++) acc[c] = 0ull;

    const int nk = Kd >> 4;
    float4 pa, pw;

    {
        pa = *(const float4*)&A[(row0 + lrow) * Kd + lk];
        pw = *(const float4*)&W[(col0 + lrow) * Kd + lk];
        As[0][lk + 0][lrow] = pa.x; As[0][lk + 1][lrow] = pa.y;
        As[0][lk + 2][lrow] = pa.z; As[0][lk + 3][lrow] = pa.w;
        Ws[0][lk + 0][lrow] = pw.x; Ws[0][lk + 1][lrow] = pw.y;
        Ws[0][lk + 2][lrow] = pw.z; Ws[0][lk + 3][lrow] = pw.w;
    }
    __syncthreads();

    for (int t = 0; t < nk; t++) {
        const int cur = t & 1;
        if (t + 1 < nk) {
            const int k0 = (t + 1) * 16;
            pa = *(const float4*)&A[(row0 + lrow) * Kd + k0 + lk];
            pw = *(const float4*)&W[(col0 + lrow) * Kd + k0 + lk];
        }

#pragma unroll
        for (int kk = 0; kk < 16; kk++) {
            const unsigned long long a =
                *(const unsigned long long*)&As[cur][kk][ty * 2];
            const float4 w = *(const float4*)&Ws[cur][kk][tx * 4];
            ffma2(acc[0], a, dup2(w.x));
            ffma2(acc[1], a, dup2(w.y));
            ffma2(acc[2], a, dup2(w.z));
            ffma2(acc[3], a, dup2(w.w));
        }

        if (t + 1 < nk) {
            const int nb = (t + 1) & 1;
            As[nb][lk + 0][lrow] = pa.x; As[nb][lk + 1][lrow] = pa.y;
            As[nb][lk + 2][lrow] = pa.z; As[nb][lk + 3][lrow] = pa.w;
            Ws[nb][lk + 0][lrow] = pw.x; Ws[nb][lk + 1][lrow] = pw.y;
            Ws[nb][lk + 2][lrow] = pw.z; Ws[nb][lk + 3][lrow] = pw.w;
            __syncthreads();
        }
    }

    float bz[4];
#pragma unroll
    for (int c = 0; c < 4; c++) bz[c] = bias[col0 + tx * 4 + c];

    float r0[4], r1[4];
#pragma unroll
    for (int c = 0; c < 4; c++) unpack2(acc[c], r0[c], r1[c]);
    float* Crow0 = C + (row0 + ty * 2) * N + col0 + tx * 4;
    float* Crow1 = Crow0 + N;
    float4 o;
    o.x = siluf(r0[0] + bz[0]); o.y = siluf(r0[1] + bz[1]);
    o.z = siluf(r0[2] + bz[2]); o.w = siluf(r0[3] + bz[3]);
    *(float4*)Crow0 = o;
    o.x = siluf(r1[0] + bz[0]); o.y = siluf(r1[1] + bz[1]);
    o.z = siluf(r1[2] + bz[2]); o.w = siluf(r1[3] + bz[3]);
    *(float4*)Crow1 = o;
}

// ---------------------------------------------------------------------------
// QKV GEMM: 32x64 tile, 128 threads, 4x4 per thread (unchanged from R5).
// ---------------------------------------------------------------------------
__global__ void __launch_bounds__(128) gemm_silu_kernel(
    const float* __restrict__ A,
    const float* __restrict__ W0, const float* __restrict__ W1, const float* __restrict__ W2,
    const float* __restrict__ bias0, const float* __restrict__ bias1, const float* __restrict__ bias2,
    float* __restrict__ C0, float* __restrict__ C1, float* __restrict__ C2,
    int N, int Kd)
{
    const float* W    = (blockIdx.z == 0) ? W0    : (blockIdx.z == 1) ? W1    : W2;
    const float* bias = (blockIdx.z == 0) ? bias0 : (blockIdx.z == 1) ? bias1 : bias2;
    float*       C    = (blockIdx.z == 0) ? C0    : (blockIdx.z == 1) ? C1    : C2;

    __shared__ float As[2][16][36];
    __shared__ float Ws[2][16][68];

    const int tid  = threadIdx.x;
    const int tx   = tid & 15;
    const int ty   = tid >> 4;
    const int row0 = blockIdx.y * 32;
    const int col0 = blockIdx.x * 64;

    const int alrow = tid >> 2;
    const int alk   = (tid & 3) * 4;
    const int wlrow = tid >> 1;
    const int wlk   = (tid & 1) * 8;

    unsigned long long acc[2][4];
#pragma unroll
    for (int p = 0; p < 2; p++)
#pragma unroll
        for (int c = 0; c < 4; c++) acc[p][c] = 0ull;

    const int nk = Kd >> 4;
    float4 pa, pw0, pw1;

    {
        pa  = *(const float4*)&A[(row0 + alrow) * Kd + alk];
        pw0 = *(const float4*)&W[(col0 + wlrow) * Kd + wlk];
        pw1 = *(const float4*)&W[(col0 + wlrow) * Kd + wlk + 4];
        As[0][alk + 0][alrow] = pa.x; As[0][alk + 1][alrow] = pa.y;
        As[0][alk + 2][alrow] = pa.z; As[0][alk + 3][alrow] = pa.w;
        Ws[0][wlk + 0][wlrow] = pw0.x; Ws[0][wlk + 1][wlrow] = pw0.y;
        Ws[0][wlk + 2][wlrow] = pw0.z; Ws[0][wlk + 3][wlrow] = pw0.w;
        Ws[0][wlk + 4][wlrow] = pw1.x; Ws[0][wlk + 5][wlrow] = pw1.y;
        Ws[0][wlk + 6][wlrow] = pw1.z; Ws[0][wlk + 7][wlrow] = pw1.w;
    }
    __syncthreads();

    for (int t = 0; t < nk; t++) {
        const int cur = t & 1;
        if (t + 1 < nk) {
            const int k0 = (t + 1) * 16;
            pa  = *(const float4*)&A[(row0 + alrow) * Kd + k0 + alk];
            pw0 = *(const float4*)&W[(col0 + wlrow) * Kd + k0 + wlk];
            pw1 = *(const float4*)&W[(col0 + wlrow) * Kd + k0 + wlk + 4];
        }

#pragma unroll
        for (int kk = 0; kk < 16; kk++) {
            const ulonglong2 a =
                *(const ulonglong2*)&As[cur][kk][ty * 4];
            const float4 w = *(const float4*)&Ws[cur][kk][tx * 4];
            const unsigned long long w0 = dup2(w.x);
            const unsigned long long w1 = dup2(w.y);
            const unsigned long long w2 = dup2(w.z);
            const unsigned long long w3 = dup2(w.w);
            ffma2(acc[0][0], a.x, w0);
            ffma2(acc[1][0], a.y, w0);
            ffma2(acc[0][1], a.x, w1);
            ffma2(acc[1][1], a.y, w1);
            ffma2(acc[0][2], a.x, w2);
            ffma2(acc[1][2], a.y, w2);
            ffma2(acc[0][3], a.x, w3);
            ffma2(acc[1][3], a.y, w3);
        }

        if (t + 1 < nk) {
            const int nb = (t + 1) & 1;
            As[nb][alk + 0][alrow] = pa.x; As[nb][alk + 1][alrow] = pa.y;
            As[nb][alk + 2][alrow] = pa.z; As[nb][alk + 3][alrow] = pa.w;
            Ws[nb][wlk + 0][wlrow] = pw0.x; Ws[nb][wlk + 1][wlrow] = pw0.y;
            Ws[nb][wlk + 2][wlrow] = pw0.z; Ws[nb][wlk + 3][wlrow] = pw0.w;
            Ws[nb][wlk + 4][wlrow] = pw1.x; Ws[nb][wlk + 5][wlrow] = pw1.y;
            Ws[nb][wlk + 6][wlrow] = pw1.z; Ws[nb][wlk + 7][wlrow] = pw1.w;
            __syncthreads();
        }
    }

    float bz[4];
#pragma unroll
    for (int c = 0; c < 4; c++) bz[c] = bias[col0 + tx * 4 + c];

#pragma unroll
    for (int p = 0; p < 2; p++) {
        float r0[4], r1[4];
#pragma unroll
        for (int c = 0; c < 4; c++) unpack2(acc[p][c], r0[c], r1[c]);
        float* Crow0 = C + (row0 + ty * 4 + 2 * p) * N + col0 + tx * 4;
        float* Crow1 = Crow0 + N;
        float4 o;
        o.x = siluf(r0[0] + bz[0]); o.y = siluf(r0[1] + bz[1]);
        o.z = siluf(r0[2] + bz[2]); o.w = siluf(r0[3] + bz[3]);
        *(float4*)Crow0 = o;
        o.x = siluf(r1[0] + bz[0]); o.y = siluf(r1[1] + bz[1]);
        o.z = siluf(r1[2] + bz[2]); o.w = siluf(r1[3] + bz[3]);
        *(float4*)Crow1 = o;
    }
}

// ---------------------------------------------------------------------------
// Attention v4: rank-1 softmax.
//  - small q (<= qc): exact Taylor-moment evaluation (33 terms).
//  - large q: K hybrid-bitonic-sorted descending with SYMMETRIC comparator
//    (both partners compute identical (vlo,vhi) -> tie-safe); per-thread
//    binary-searched trip count; n >= 1 guard.
//  - warp coherence via atomic bucket partition on n.
// ---------------------------------------------------------------------------
__global__ void __launch_bounds__(H2) attn_out_kernel(
    const float* __restrict__ W_out,
    const float* __restrict__ b_out,
    float* __restrict__ out)
{
    __shared__ float Ksrt[H2];
    __shared__ float Vsrt[H2];
    __shared__ float qperm[H2];
    __shared__ int   nperm[H2];
    __shared__ int   idxperm[H2];
    __shared__ float cs[H2];
    __shared__ float red[16];
    __shared__ float s_kmax;
    __shared__ float m1p[NPOLY][16];
    __shared__ float mvp[NPOLY][16];
    __shared__ float c1[NPOLY], cV[NPOLY];
    __shared__ int   cnt[8], base[8];
    __shared__ float ys[32];

    const int b = blockIdx.x;
    const int t = threadIdx.x;
    const int wid = t >> 5, lane = t & 31;

    const float kv = g_K[b * H2 + t];
    const float vv = g_V[b * H2 + t];
    const float qv = g_Q[b * H2 + t];

    if (t < 8) cnt[t] = 0;

    // ---- block max of K ----
    float kmx = kv;
#pragma unroll
    for (int o = 16; o; o >>= 1)
        kmx = fmaxf(kmx, __shfl_xor_sync(0xFFFFFFFFu, kmx, o));
    if (lane == 0) red[wid] = kmx;
    __syncthreads();
    if (t == 0) {
        float a = red[0];
#pragma unroll
        for (int i = 1; i < 16; i++) a = fmaxf(a, red[i]);
        s_kmax = a;
    }
    __syncthreads();
    const float kmax = s_kmax;
    const float S    = fmaxf(kmax, 0.3f);
    const float qc   = fmaxf(7.0f / S, 0.2786f);

    // ---- moments from registers: mu_m = sum r^m, muV_m = sum r^m * V ----
    {
        const float r = kv / S;
        float pw = 1.0f;
#pragma unroll 1
        for (int m = 0; m < NPOLY; m++) {
            float s1 = pw, sv = pw * vv;
#pragma unroll
            for (int o = 16; o; o >>= 1) {
                s1 += __shfl_xor_sync(0xFFFFFFFFu, s1, o);
                sv += __shfl_xor_sync(0xFFFFFFFFu, sv, o);
            }
            if (lane == 0) { m1p[m][wid] = s1; mvp[m][wid] = sv; }
            pw *= r;
        }
    }

    // ---- hybrid bitonic sort of K descending, payload V ----
    // SYMMETRIC comparator: both partners compute the same (vlo, vhi), so
    // decisions are always complementary (ties -> harmless full swap).
    {
        float v = kv, pl = vv;
#pragma unroll 1
        for (int k = 2; k <= H2; k <<= 1) {
#pragma unroll 1
            for (int j = k >> 1; j > 0; j >>= 1) {
                float ov, op;
                if (j >= 32) {
                    __syncthreads();
                    Ksrt[t] = v; Vsrt[t] = pl;
                    __syncthreads();
                    ov = Ksrt[t ^ j]; op = Vsrt[t ^ j];
                } else {
                    ov = __shfl_xor_sync(0xFFFFFFFFu, v, j);
                    op = __shfl_xor_sync(0xFFFFFFFFu, pl, j);
                }
                const bool lower = (t & j) == 0;
                const bool dir   = (t & k) != 0;     // descending overall
                const float vlo = lower ? v : ov;
                const float vhi = lower ? ov : v;
                if ((vlo > vhi) == dir) { v = ov; pl = op; }
            }
        }
        __syncthreads();
        Ksrt[t] = v; Vsrt[t] = pl;
    }
    __syncthreads();

    // ---- finalize moment coefficients ----
    if (t < NPOLY) {
        float a = 0.0f;
#pragma unroll
        for (int i = 0; i < 16; i++) a += m1p[t][i];
        c1[t] = a * c_invfact[t];
    } else if (t >= 64 && t < 64 + NPOLY) {
        const int m = t - 64;
        float a = 0.0f;
#pragma unroll
        for (int i = 0; i < 16; i++) a += mvp[m][i];
        cV[m] = a * c_invfact[m];
    }

    // ---- per-thread trip count + bucket ----
    int bkt, n = 0;
    if (qv <= qc) {
        bkt = 6;  // poly
    } else {
        const float cutval = kmax - 18.714974f / qv;  // 27 / log2(e)
        int lo = 0, hi = H2;
#pragma unroll
        for (int s = 0; s < 9; s++) {
            const int mid = (lo + hi) >> 1;
            if (Ksrt[mid] >= cutval) lo = mid + 1; else hi = mid;
        }
        n = (lo < 1) ? 1 : lo;   // guard: never 0 trips (0/0 -> NaN)
        bkt = (n <= 16) ? 0 : (n <= 32) ? 1 : (n <= 64) ? 2
            : (n <= 128) ? 3 : (n <= 256) ? 4 : 5;
    }
    const int rank = atomicAdd(&cnt[bkt], 1);
    __syncthreads();
    if (t == 0) {
        int s = 0;
#pragma unroll
        for (int i = 0; i < 8; i++) { base[i] = s; s += cnt[i]; }
    }
    __syncthreads();
    {
        const int slot = base[bkt] + rank;
        qperm[slot]   = qv;
        nperm[slot]   = (bkt == 6) ? -1 : n;
        idxperm[slot] = t;
    }
    __syncthreads();

    // ---- compute ctx at my slot ----
    {
        const float q   = qperm[t];
        const int   nn  = nperm[t];
        const int   oid = idxperm[t];
        float ctx;
        if (nn < 0) {
            const float tv = q * S;
            float num = cV[NPOLY - 1], den = c1[NPOLY - 1];
#pragma unroll
            for (int m = NPOLY - 2; m >= 0; m--) {
                num = fmaf(num, tv, cV[m]);
                den = fmaf(den, tv, c1[m]);
            }
            ctx = __fdividef(num, den);
        } else {
            const float q2 = q * 1.44269504f;
            const float c2 = -q2 * kmax;
            float sE = 0.0f, sEV = 0.0f;
            for (int j = 0; j < nn; j++) {
                const float e = ex2f(fmaf(q2, Ksrt[j], c2));
                sE += e;
                sEV = fmaf(e, Vsrt[j], sEV);
            }
            ctx = __fdividef(sEV, sE);
        }
        cs[oid] = siluf(ctx);
    }
    __syncthreads();

    // ---- output projection: warp w handles n = w and n = w + 16 ----
#pragma unroll
    for (int r = 0; r < 2; r++) {
        const int no = wid + 16 * r;
        if (no < OUT_DIM) {
            const float* Wr = W_out + no * H2;
            float s = 0.0f;
#pragma unroll
            for (int kk = 0; kk < 16; kk++)
                s = fmaf(cs[lane + 32 * kk], Wr[lane + 32 * kk], s);
#pragma unroll
            for (int o = 16; o; o >>= 1)
                s += __shfl_xor_sync(0xFFFFFFFFu, s, o);
            if (lane == 0) ys[no] = siluf(s + b_out[no]);
        }
    }
    __syncthreads();

    if (t == 0) {
        float g[5];
#pragma unroll
        for (int gi = 0; gi < 5; gi++) {
            float s = 0.0f;
#pragma unroll
            for (int i = 0; i < 5; i++) {
                const float yv = ys[gi * 5 + i];
                s = fmaf(yv, yv, s);
            }
            g[gi] = s;
        }
        const float m11 = g[0], m12 = g[1], m21 = g[2], m22 = g[3], mpp = g[4];
        const float q0 = ys[0], q1 = ys[1], q2 = ys[2], q3 = ys[3];
        const float quad = m11 * (q0 * q0 + q1 * q1)
                         + (m12 + m21) * (q0 * q2 + q1 * q3)
                         + m22 * (q2 * q2 + q3 * q3);
        out[b] = quad + mpp;
    }
}

// ---------------------------------------------------------------------------
extern "C" void kernel_launch(void* const* d_in, const int* in_sizes, int n_in,
                              void* d_out, int out_size)
{
    const float* x     = (const float*)d_in[0];
    // d_in[1] = na (int32, always 4) — unused (q = y[:, :4] hardcoded)
    const float* W_in  = (const float*)d_in[2];
    const float* b_in  = (const float*)d_in[3];
    const float* Aq    = (const float*)d_in[4];
    const float* Bq    = (const float*)d_in[5];
    const float* Ak    = (const float*)d_in[6];
    const float* Bk    = (const float*)d_in[7];
    const float* Av    = (const float*)d_in[8];
    const float* Bv    = (const float*)d_in[9];
    const float* W_out = (const float*)d_in[10];
    const float* b_out = (const float*)d_in[11];
    float* out = (float*)d_out;

    float *h, *Qp, *Kp, *Vp;
    cudaGetSymbolAddress((void**)&h,  g_h);
    cudaGetSymbolAddress((void**)&Qp, g_Q);
    cudaGetSymbolAddress((void**)&Kp, g_K);
    cudaGetSymbolAddress((void**)&Vp, g_V);

    // h = silu(x @ W_in^T + b_in)
    gemm1_silu_kernel<<<dim3(16, 16), 128>>>(x, W_in, b_in, h, H2, IN_DIM);

    // Q,K,V = silu(h @ A*^T + B*) fused via grid.z
    gemm_silu_kernel<<<dim3(8, 16, 3), 128>>>(
        h, Aq, Ak, Av, Bq, Bk, Bv, Qp, Kp, Vp, H2, H2);

    // rank-1 softmax attention (poly + truncated-exp, bucketed) + epilogue
    attn_out_kernel<<<BSZ, H2>>>(W_out, b_out, out);
}